// round 17
// baseline (speedup 1.0000x reference)
#include <cuda_runtime.h>
#include <math.h>
#include <cstdint>

#define T    4096
#define S    256
#define NCTA 16       // cluster size (non-portable, fits one GPC)
#define WPC  4        // DP warps per CTA; each warp owns 4 state rows
#define D    16       // publication ring depth
#define NW   112      // backpointer worker CTAs (grid = 16 + 112 = 8 clusters)
#define NB   64       // backtrace chunks
#define CH   64       // steps per chunk (NB*CH == T)

// ---- device scratch (no cudaMalloc allowed) ----
__device__ int g_bp[T * S];          // backpointers (filled by workers DURING the DP)
__device__ int g_link[NB][S];        // composed chunk maps
__device__ unsigned g_prog[64];      // per-DP-warp progress (vout up to t stored)

__device__ __forceinline__ uint32_t smem_u32(const void* p) {
    uint32_t a;
    asm("{ .reg .u64 t; cvta.to.shared.u64 t, %1; cvt.u32.u64 %0, t; }"
        : "=r"(a) : "l"(p));
    return a;
}
__device__ __forceinline__ uint32_t ctarank() {
    uint32_t r;
    asm("mov.u32 %0, %%cluster_ctarank;" : "=r"(r));
    return r;
}
__device__ __forceinline__ uint32_t mapa_u32(uint32_t addr, uint32_t rank) {
    uint32_t rem;
    asm("mapa.shared::cluster.u32 %0, %1, %2;" : "=r"(rem) : "r"(addr), "r"(rank));
    return rem;
}
__device__ __forceinline__ void lds_v2_vol(uint32_t addr,
                                           unsigned long long& a, unsigned long long& b) {
    asm volatile("ld.volatile.shared.v2.u64 {%0,%1}, [%2];"
                 : "=l"(a), "=l"(b) : "r"(addr));
}
__device__ __forceinline__ void st_cluster_v2u64(uint32_t addr,
                                                 unsigned long long a, unsigned long long b) {
    asm volatile("st.shared::cluster.v2.u64 [%0], {%1,%2};"
                 :: "r"(addr), "l"(a), "l"(b) : "memory");
}
__device__ __forceinline__ void st_rel_u32(unsigned* p, unsigned v) {
    asm volatile("st.release.gpu.global.u32 [%0], %1;" :: "l"(p), "r"(v) : "memory");
}
__device__ __forceinline__ unsigned ld_acq_u32(const unsigned* p) {
    unsigned v;
    asm volatile("ld.acquire.gpu.global.u32 %0, [%1];" : "=r"(v) : "l"(p) : "memory");
    return v;
}

__global__ void sv_reset() {
    if (threadIdx.x < 64) g_prog[threadIdx.x] = 0u;
}

// ============ merged kernel: DP cluster (bid<16) + bp workers (bid>=16) ============
__global__ __launch_bounds__(128, 1) __cluster_dims__(NCTA, 1, 1)
void sv_main(const float* __restrict__ pot, float* __restrict__ out) {
    __shared__ alignas(16) unsigned long long vbuf[D][S];  // DP ring (32 KB)
    __shared__ float vprev[S];                             // worker vprev (1 KB)

    const int tid  = threadIdx.x;
    const int w    = tid >> 5;
    const int lane = tid & 31;
    float* vout = out + T;                        // v[t*S + s]

    if (blockIdx.x < NCTA) {
        // ================= DP path (numerics pinned to R16) =================
        const uint32_t rank = ctarank();
        const int s0 = ((int)rank * WPC + w) * 4;     // this warp's four state rows
        const int gw = (int)rank * WPC + w;           // global DP warp id (0..63)

        for (int i = tid; i < D * S; i += 128)
            ((unsigned long long*)vbuf)[i] = ~0ULL;
        if (rank == 0)
            for (int i = tid; i < S; i += 128) vout[i] = pot[i];   // v0 row
        __syncthreads();
        asm volatile("barrier.cluster.arrive.aligned;" ::: "memory");
        asm volatile("barrier.cluster.wait.aligned;" ::: "memory");

        const float* prow0 = pot + (size_t)(s0 + 0) * S;
        const float* prow1 = pot + (size_t)(s0 + 1) * S;
        const float* prow2 = pot + (size_t)(s0 + 2) * S;
        const float* prow3 = pot + (size_t)(s0 + 3) * S;
        const int c0 = 4 * lane;
        const int c1 = 128 + 4 * lane;

        float K0 = pot[s0], K1 = pot[s0 + 1], K2 = pot[s0 + 2], K3 = pot[s0 + 3];

        uint32_t rem_base = 0;
        if (lane < NCTA)
            rem_base = mapa_u32(smem_u32(&vbuf[0][s0]), (uint32_t)lane);
        const uint32_t lb = smem_u32(&vbuf[0][0]);
        const uint32_t la0 = lb + (uint32_t)c0 * 8u;
        const uint32_t la1 = lb + (uint32_t)(c0 + 2) * 8u;
        const uint32_t la2 = lb + (uint32_t)c1 * 8u;
        const uint32_t la3 = lb + (uint32_t)(c1 + 2) * 8u;

        if (lane < NCTA) {
            st_cluster_v2u64(rem_base,
                             (unsigned long long)__float_as_uint(K0),
                             (unsigned long long)__float_as_uint(K1));
            st_cluster_v2u64(rem_base + 16,
                             (unsigned long long)__float_as_uint(K2),
                             (unsigned long long)__float_as_uint(K3));
        }

        float4 pA0 = *(const float4*)(prow0 + (size_t)S * S + c0);
        float4 pB0 = *(const float4*)(prow0 + (size_t)S * S + c1);
        float4 pA1 = *(const float4*)(prow1 + (size_t)S * S + c0);
        float4 pB1 = *(const float4*)(prow1 + (size_t)S * S + c1);
        float4 pA2 = *(const float4*)(prow2 + (size_t)S * S + c0);
        float4 pB2 = *(const float4*)(prow2 + (size_t)S * S + c1);
        float4 pA3 = *(const float4*)(prow3 + (size_t)S * S + c0);
        float4 pB3 = *(const float4*)(prow3 + (size_t)S * S + c1);

        for (int t = 1; t < T; ++t) {
            const size_t nxt = (size_t)((t + 1 < T) ? (t + 1) : t) * S * S;
            float4 nA0 = *(const float4*)(prow0 + nxt + c0);
            float4 nB0 = *(const float4*)(prow0 + nxt + c1);
            float4 nA1 = *(const float4*)(prow1 + nxt + c0);
            float4 nB1 = *(const float4*)(prow1 + nxt + c1);
            float4 nA2 = *(const float4*)(prow2 + nxt + c0);
            float4 nB2 = *(const float4*)(prow2 + nxt + c1);
            float4 nA3 = *(const float4*)(prow3 + nxt + c0);
            float4 nB3 = *(const float4*)(prow3 + nxt + c1);

            const uint32_t bo = (uint32_t)((t - 1) & (D - 1)) * (S * 8u);
            const unsigned tg = (unsigned)(t - 1);
            unsigned long long a0, a1, a2, a3, b0, b1, b2, b3;
            for (;;) {
                lds_v2_vol(la0 + bo, a0, a1);
                lds_v2_vol(la1 + bo, a2, a3);
                lds_v2_vol(la2 + bo, b0, b1);
                lds_v2_vol(la3 + bo, b2, b3);
                bool ok = ((unsigned)(a0 >> 32) == tg) & ((unsigned)(a1 >> 32) == tg) &
                          ((unsigned)(a2 >> 32) == tg) & ((unsigned)(a3 >> 32) == tg) &
                          ((unsigned)(b0 >> 32) == tg) & ((unsigned)(b1 >> 32) == tg) &
                          ((unsigned)(b2 >> 32) == tg) & ((unsigned)(b3 >> 32) == tg);
                if (__all_sync(0xffffffffu, ok)) break;
            }

            const float v0a = __uint_as_float((unsigned)a0);
            const float v1a = __uint_as_float((unsigned)a1);
            const float v2a = __uint_as_float((unsigned)a2);
            const float v3a = __uint_as_float((unsigned)a3);
            const float v0b = __uint_as_float((unsigned)b0);
            const float v1b = __uint_as_float((unsigned)b1);
            const float v2b = __uint_as_float((unsigned)b2);
            const float v3b = __uint_as_float((unsigned)b3);

            float e0 = __expf(v0a + pA0.x - K0) + __expf(v1a + pA0.y - K0) +
                       __expf(v2a + pA0.z - K0) + __expf(v3a + pA0.w - K0) +
                       __expf(v0b + pB0.x - K0) + __expf(v1b + pB0.y - K0) +
                       __expf(v2b + pB0.z - K0) + __expf(v3b + pB0.w - K0);
            float e1 = __expf(v0a + pA1.x - K1) + __expf(v1a + pA1.y - K1) +
                       __expf(v2a + pA1.z - K1) + __expf(v3a + pA1.w - K1) +
                       __expf(v0b + pB1.x - K1) + __expf(v1b + pB1.y - K1) +
                       __expf(v2b + pB1.z - K1) + __expf(v3b + pB1.w - K1);
            float e2 = __expf(v0a + pA2.x - K2) + __expf(v1a + pA2.y - K2) +
                       __expf(v2a + pA2.z - K2) + __expf(v3a + pA2.w - K2) +
                       __expf(v0b + pB2.x - K2) + __expf(v1b + pB2.y - K2) +
                       __expf(v2b + pB2.z - K2) + __expf(v3b + pB2.w - K2);
            float e3 = __expf(v0a + pA3.x - K3) + __expf(v1a + pA3.y - K3) +
                       __expf(v2a + pA3.z - K3) + __expf(v3a + pA3.w - K3) +
                       __expf(v0b + pB3.x - K3) + __expf(v1b + pB3.y - K3) +
                       __expf(v2b + pB3.z - K3) + __expf(v3b + pB3.w - K3);

            #pragma unroll
            for (int o = 16; o; o >>= 1) {
                e0 += __shfl_xor_sync(0xffffffffu, e0, o);
                e1 += __shfl_xor_sync(0xffffffffu, e1, o);
                e2 += __shfl_xor_sync(0xffffffffu, e2, o);
                e3 += __shfl_xor_sync(0xffffffffu, e3, o);
            }

            float v0 = K0 + __logf(e0);
            float v1 = K1 + __logf(e1);
            float v2 = K2 + __logf(e2);
            float v3 = K3 + __logf(e3);

            const unsigned long long tagw = (unsigned long long)(unsigned)t << 32;
            const uint32_t off = (uint32_t)(t & (D - 1)) * (S * 8u);
            if (lane < NCTA) {
                st_cluster_v2u64(rem_base + off,
                                 tagw | (unsigned long long)__float_as_uint(v0),
                                 tagw | (unsigned long long)__float_as_uint(v1));
                st_cluster_v2u64(rem_base + off + 16,
                                 tagw | (unsigned long long)__float_as_uint(v2),
                                 tagw | (unsigned long long)__float_as_uint(v3));
            }
            if (lane == 0) {
                *(float4*)(vout + (size_t)t * S + s0) = make_float4(v0, v1, v2, v3);
                if ((t & 15) == 0) st_rel_u32(&g_prog[gw], (unsigned)t);
            }

            K0 = v0; K1 = v1; K2 = v2; K3 = v3;
            pA0 = nA0; pB0 = nB0; pA1 = nA1; pB1 = nB1;
            pA2 = nA2; pB2 = nB2; pA3 = nA3; pB3 = nB3;
        }

        if (lane == 0) st_rel_u32(&g_prog[gw], (unsigned)T);

        asm volatile("barrier.cluster.arrive.aligned;" ::: "memory");
        asm volatile("barrier.cluster.wait.aligned;" ::: "memory");
    } else {
        // ================= backpointer worker path =================
        const int wk = (int)blockIdx.x - NCTA;
        const int c0 = 4 * lane;
        const int c1 = 128 + 4 * lane;

        for (int t = 1 + wk; t < T; t += NW) {
            // wait until all 64 DP warps have stored vout up to t-1
            if (t > 1) {
                if (w == 0) {
                    const unsigned tgt = (unsigned)(t - 1);
                    for (;;) {
                        unsigned p0 = ld_acq_u32(&g_prog[lane * 2]);
                        unsigned p1 = ld_acq_u32(&g_prog[lane * 2 + 1]);
                        if (__all_sync(0xffffffffu, (p0 >= tgt) & (p1 >= tgt))) break;
                        __nanosleep(512);
                    }
                }
                __syncthreads();   // publish acquire visibility CTA-wide
            }

            // load v_{t-1}
            if (tid < S) { }
            for (int i = tid; i < S; i += 128)
                vprev[i] = (t == 1) ? pot[i] : vout[(size_t)(t - 1) * S + i];
            __syncthreads();

            float4 vA = *(const float4*)(vprev + c0);
            float4 vB = *(const float4*)(vprev + c1);

            // 4 warps x 64 rows; same math/tie-break as reference argmax
            for (int r = 0; r < 64; ++r) {
                const int s = w * 64 + r;
                const float* prow = pot + (size_t)t * S * S + (size_t)s * S;
                float4 pA = *(const float4*)(prow + c0);
                float4 pB = *(const float4*)(prow + c1);

                float sc[8];
                sc[0] = vA.x + pA.x;  sc[1] = vA.y + pA.y;
                sc[2] = vA.z + pA.z;  sc[3] = vA.w + pA.w;
                sc[4] = vB.x + pB.x;  sc[5] = vB.y + pB.y;
                sc[6] = vB.z + pB.z;  sc[7] = vB.w + pB.w;

                float m = sc[0]; int mi = c0;
                #pragma unroll
                for (int k = 1; k < 8; ++k) {
                    int c = (k < 4) ? (c0 + k) : (c1 + (k - 4));
                    if (sc[k] > m) { m = sc[k]; mi = c; }
                }
                #pragma unroll
                for (int o = 16; o; o >>= 1) {
                    float om = __shfl_xor_sync(0xffffffffu, m, o);
                    int   oi = __shfl_xor_sync(0xffffffffu, mi, o);
                    if (om > m || (om == m && oi < mi)) { m = om; mi = oi; }
                }
                if (lane == 0) g_bp[t * S + s] = mi;
            }
            __syncthreads();   // vprev reused next iteration
        }
    }
}

// compose each chunk's backpointer map
__global__ void sv_link() {
    int b = blockIdx.x;
    if (b == 0) return;
    int cur = threadIdx.x;
    int tlo = b * CH;
    for (int t = tlo + CH - 2; t >= tlo - 1; --t)
        cur = g_bp[(t + 1) * S + cur];
    g_link[b][threadIdx.x] = cur;
}

__global__ void sv_back(float* __restrict__ out) {
    __shared__ float sm[8];
    __shared__ int   si[8];
    __shared__ int   sE[NB];
    const int tid = threadIdx.x, lane = tid & 31;

    const float* vlast = out + T + (size_t)(T - 1) * S;
    float m = vlast[tid]; int mi = tid;
    #pragma unroll
    for (int o = 16; o; o >>= 1) {
        float om = __shfl_xor_sync(0xffffffffu, m, o);
        int   oi = __shfl_xor_sync(0xffffffffu, mi, o);
        if (om > m || (om == m && oi < mi)) { m = om; mi = oi; }
    }
    if (lane == 0) { sm[tid >> 5] = m; si[tid >> 5] = mi; }
    __syncthreads();

    if (tid == 0) {
        m = sm[0]; mi = si[0];
        #pragma unroll
        for (int w = 1; w < 8; ++w)
            if (sm[w] > m || (sm[w] == m && si[w] < mi)) { m = sm[w]; mi = si[w]; }
        int e = mi;
        sE[NB - 1] = e;
        for (int b = NB - 1; b >= 1; --b) { e = g_link[b][e]; sE[b - 1] = e; }
    }
    __syncthreads();

    if (tid < NB) {
        int b = tid;
        int cur = sE[b];
        out[b * CH + CH - 1] = (float)cur;
        for (int t = b * CH + CH - 2; t >= b * CH; --t) {
            cur = g_bp[(t + 1) * S + cur];
            out[t] = (float)cur;
        }
    }
}

extern "C" void kernel_launch(void* const* d_in, const int* in_sizes, int n_in,
                              void* d_out, int out_size) {
    const float* pot = (const float*)d_in[0];
    float* out = (float*)d_out;

    cudaFuncSetAttribute(sv_main, cudaFuncAttributeNonPortableClusterSizeAllowed, 1);

    sv_reset<<<1, 64>>>();
    sv_main<<<NCTA + NW, 128>>>(pot, out);
    sv_link<<<NB, 256>>>();
    sv_back<<<1, 256>>>(out);
}